// round 3
// baseline (speedup 1.0000x reference)
#include <cuda_runtime.h>
#include <math.h>

#define NB 8
#define H 256
#define W 256
#define H2 512
#define W2 512
#define HW (H*W)

typedef unsigned long long u64;

// packed fp32x2 helpers (FFMA2 — only reachable via PTX, per SASS_QUICKREF)
__device__ __forceinline__ u64 pk2(float lo, float hi) {
    u64 r; asm("mov.b64 %0,{%1,%2};" : "=l"(r) : "f"(lo), "f"(hi)); return r;
}
__device__ __forceinline__ void fma2(u64& acc, u64 a, u64 b) {
    asm("fma.rn.f32x2 %0,%1,%2,%0;" : "+l"(acc) : "l"(a), "l"(b));
}
__device__ __forceinline__ float2 upk(u64 v) {
    float2 r; asm("mov.b64 {%0,%1},%2;" : "=f"(r.x), "=f"(r.y) : "l"(v)); return r;
}

// ---------------- scratch (device globals; no allocation) ----------------
__device__ float g_curr[NB*3*HW];    // resized right image
__device__ float g_feats[NB*12*HW];  // concat features
__device__ float g_x1[NB*32*HW];     // conv1 out
__device__ float g_x2[NB*64*HW];     // conv2 out
__device__ float g_aff[NB*8*HW];     // conv3 out (affinities)
__device__ float g_s1[32], g_bb1[32], g_s2[64], g_bb2[64]; // folded BN

// ---------------- BN fold ----------------
__global__ void k_bnfold(const float* __restrict__ g1, const float* __restrict__ b1,
                         const float* __restrict__ m1, const float* __restrict__ v1,
                         const float* __restrict__ g2, const float* __restrict__ b2,
                         const float* __restrict__ m2, const float* __restrict__ v2) {
    int i = threadIdx.x;
    if (i < 32) { float s = g1[i] * rsqrtf(v1[i] + 1e-5f); g_s1[i] = s; g_bb1[i] = b1[i] - m1[i] * s; }
    if (i < 64) { float s = g2[i] * rsqrtf(v2[i] + 1e-5f); g_s2[i] = s; g_bb2[i] = b2[i] - m2[i] * s; }
}

// ---------------- resize right (2x2 avg pool) ----------------
__global__ void k_resize_right(const float* __restrict__ right) {
    int idx = blockIdx.x * blockDim.x + threadIdx.x;
    if (idx >= NB*3*HW) return;
    int x = idx & 255;
    int y = (idx >> 8) & 255;
    int nc = idx >> 16;
    int c = nc % 3, n = nc / 3;
    const float* src = right + ((size_t)(n*3 + c) * H2 + 2*y) * W2 + 2*x;
    float v = 0.25f * (src[0] + src[1] + src[W2] + src[W2+1]);
    g_curr[idx] = v;
    g_feats[((size_t)(n*12 + 6 + c) * H + y) * W + x] = v;
}

// ---------------- left resize + normal copy + LR-warp error ----------------
__global__ void k_feats(const float* __restrict__ left, const float* __restrict__ normal,
                        const float* __restrict__ disp) {
    int idx = blockIdx.x * blockDim.x + threadIdx.x;
    if (idx >= NB*3*HW) return;
    int x = idx & 255;
    int y = (idx >> 8) & 255;
    int nc = idx >> 16;
    int c = nc % 3, n = nc / 3;

    const float* srcL = left + ((size_t)(n*3 + c) * H2 + 2*y) * W2 + 2*x;
    float l = 0.25f * (srcL[0] + srcL[1] + srcL[W2] + srcL[W2+1]);

    size_t base = ((size_t)(n*12) * H + y) * W + x;
    g_feats[base + (size_t)c * HW]     = normal[((size_t)(n*3 + c) * H + y) * W + x];
    g_feats[base + (size_t)(3+c) * HW] = l;

    float d = disp[((size_t)n * H + y) * W + x];
    float xs = (float)x - d;
    float x0f = floorf(xs);
    float frac = xs - x0f;
    int x0i = (int)x0f;
    int x1i = x0i + 1;
    float v0 = (x0i >= 0 && x0i < W) ? 1.f : 0.f;
    float v1 = (x1i >= 0 && x1i < W) ? 1.f : 0.f;
    int x0c = min(max(x0i, 0), W-1);
    int x1c = min(max(x1i, 0), W-1);
    const float* r = g_curr + ((size_t)(n*3 + c) * H + y) * W;
    float warped = (r[x0c] * v0) * (1.f - frac) + (r[x1c] * v1) * frac;
    g_feats[base + (size_t)(9+c) * HW] = fabsf(l - warped);
}

// ================= conv1: 12 -> 32, 3x3, pad 1, BN+ReLU (FFMA2) =================
// 128 thr, tile 64x16, micro 4x2, 8 couts/block. grid (4,16,NB*4)
// smem row padded to 68 floats (272B) so float4 loads are 16B-aligned on every row.
__global__ void __launch_bounds__(128, 3) k_conv1(const float* __restrict__ w) {
    __shared__ float  sIn[6][18][68];        // 28.7 KB
    __shared__ float2 sWd[8*12*9];           //  6.9 KB (duplicated weights)
    int t = threadIdx.x;
    int bz = blockIdx.z;
    int n = bz >> 2, cg = bz & 3;
    int x0 = blockIdx.x * 64, y0 = blockIdx.y * 16;

    for (int i = t; i < 8*12*9; i += 128) {
        float wv = w[cg*8*108 + i];
        sWd[i] = make_float2(wv, wv);
    }

    u64 acc[8][2][2];   // [co][row][xpair]
    #pragma unroll
    for (int co = 0; co < 8; co++)
        #pragma unroll
        for (int r = 0; r < 2; r++) { acc[co][r][0] = 0ull; acc[co][r][1] = 0ull; }

    int tx = t & 15, ty = t >> 4;     // 16 x 8
    int px = tx * 4, py = ty * 2;

    for (int cc = 0; cc < 2; cc++) {
        __syncthreads();
        const int LDN = 6*18*66;      // only first 66 columns used
        for (int i = t; i < LDN; i += 128) {
            int ci = i / 1188;
            int rem = i - ci*1188;
            int yy = rem / 66;
            int xx = rem - yy*66;
            int gy = y0 + yy - 1, gx = x0 + xx - 1;
            float v = 0.f;
            if ((unsigned)gy < H && (unsigned)gx < W)
                v = g_feats[((size_t)(n*12 + cc*6 + ci) * H + gy) * W + gx];
            sIn[ci][yy][xx] = v;
        }
        __syncthreads();
        for (int ci = 0; ci < 6; ci++) {
            u64 p[4][5];
            #pragma unroll
            for (int r = 0; r < 4; r++) {
                const float* q = &sIn[ci][py + r][px];
                float4 a = *reinterpret_cast<const float4*>(q);
                float2 b = *reinterpret_cast<const float2*>(q + 4);
                p[r][0] = pk2(a.x, a.y); p[r][1] = pk2(a.y, a.z);
                p[r][2] = pk2(a.z, a.w); p[r][3] = pk2(a.w, b.x);
                p[r][4] = pk2(b.x, b.y);
            }
            #pragma unroll
            for (int co = 0; co < 8; co++) {
                const u64* wp = reinterpret_cast<const u64*>(&sWd[(co*12 + cc*6 + ci) * 9]);
                #pragma unroll
                for (int ky = 0; ky < 3; ky++)
                    #pragma unroll
                    for (int kx = 0; kx < 3; kx++) {
                        u64 wk = wp[ky*3 + kx];
                        fma2(acc[co][0][0], p[ky  ][kx  ], wk);
                        fma2(acc[co][0][1], p[ky  ][kx+2], wk);
                        fma2(acc[co][1][0], p[ky+1][kx  ], wk);
                        fma2(acc[co][1][1], p[ky+1][kx+2], wk);
                    }
            }
        }
    }

    #pragma unroll
    for (int co = 0; co < 8; co++) {
        int oc = cg*8 + co;
        float s = g_s1[oc], bo = g_bb1[oc];
        #pragma unroll
        for (int r = 0; r < 2; r++) {
            float2 v0 = upk(acc[co][r][0]);
            float2 v1 = upk(acc[co][r][1]);
            float4 o = make_float4(fmaxf(fmaf(v0.x, s, bo), 0.f),
                                   fmaxf(fmaf(v0.y, s, bo), 0.f),
                                   fmaxf(fmaf(v1.x, s, bo), 0.f),
                                   fmaxf(fmaf(v1.y, s, bo), 0.f));
            *reinterpret_cast<float4*>(g_x1 + ((size_t)(n*32 + oc) * H + y0 + py + r) * W + x0 + px) = o;
        }
    }
}

// ================= conv2: 32 -> 64, 3x3, pad 1, BN+ReLU (FFMA2) =================
// 128 thr, tile 64x16, micro 4x2, 8 couts/block. grid (4,16,NB*8). cin in 4 chunks of 8.
__global__ void __launch_bounds__(128, 3) k_conv2(const float* __restrict__ w) {
    __shared__ float  sIn[8][18][68];        // 39.2 KB
    __shared__ float2 sWd[8*8*9];            //  4.6 KB
    int t = threadIdx.x;
    int bz = blockIdx.z;
    int n = bz >> 3, cg = bz & 7;
    int x0 = blockIdx.x * 64, y0 = blockIdx.y * 16;

    u64 acc[8][2][2];
    #pragma unroll
    for (int co = 0; co < 8; co++)
        #pragma unroll
        for (int r = 0; r < 2; r++) { acc[co][r][0] = 0ull; acc[co][r][1] = 0ull; }

    int tx = t & 15, ty = t >> 4;
    int px = tx * 4, py = ty * 2;

    for (int cc = 0; cc < 4; cc++) {
        __syncthreads();
        for (int i = t; i < 8*8*9; i += 128) {
            int co = i / 72; int rem = i - co*72;
            float wv = w[(size_t)(cg*8 + co) * 288 + cc*72 + rem];
            sWd[i] = make_float2(wv, wv);
        }
        const int LDN = 8*18*66;
        for (int i = t; i < LDN; i += 128) {
            int ci = i / 1188;
            int rem = i - ci*1188;
            int yy = rem / 66;
            int xx = rem - yy*66;
            int gy = y0 + yy - 1, gx = x0 + xx - 1;
            float v = 0.f;
            if ((unsigned)gy < H && (unsigned)gx < W)
                v = g_x1[((size_t)(n*32 + cc*8 + ci) * H + gy) * W + gx];
            sIn[ci][yy][xx] = v;
        }
        __syncthreads();
        for (int ci = 0; ci < 8; ci++) {
            u64 p[4][5];
            #pragma unroll
            for (int r = 0; r < 4; r++) {
                const float* q = &sIn[ci][py + r][px];
                float4 a = *reinterpret_cast<const float4*>(q);
                float2 b = *reinterpret_cast<const float2*>(q + 4);
                p[r][0] = pk2(a.x, a.y); p[r][1] = pk2(a.y, a.z);
                p[r][2] = pk2(a.z, a.w); p[r][3] = pk2(a.w, b.x);
                p[r][4] = pk2(b.x, b.y);
            }
            #pragma unroll
            for (int co = 0; co < 8; co++) {
                const u64* wp = reinterpret_cast<const u64*>(&sWd[(co*8 + ci) * 9]);
                #pragma unroll
                for (int ky = 0; ky < 3; ky++)
                    #pragma unroll
                    for (int kx = 0; kx < 3; kx++) {
                        u64 wk = wp[ky*3 + kx];
                        fma2(acc[co][0][0], p[ky  ][kx  ], wk);
                        fma2(acc[co][0][1], p[ky  ][kx+2], wk);
                        fma2(acc[co][1][0], p[ky+1][kx  ], wk);
                        fma2(acc[co][1][1], p[ky+1][kx+2], wk);
                    }
            }
        }
    }

    #pragma unroll
    for (int co = 0; co < 8; co++) {
        int oc = cg*8 + co;
        float s = g_s2[oc], bo = g_bb2[oc];
        #pragma unroll
        for (int r = 0; r < 2; r++) {
            float2 v0 = upk(acc[co][r][0]);
            float2 v1 = upk(acc[co][r][1]);
            float4 o = make_float4(fmaxf(fmaf(v0.x, s, bo), 0.f),
                                   fmaxf(fmaf(v0.y, s, bo), 0.f),
                                   fmaxf(fmaf(v1.x, s, bo), 0.f),
                                   fmaxf(fmaf(v1.y, s, bo), 0.f));
            *reinterpret_cast<float4*>(g_x2 + ((size_t)(n*64 + oc) * H + y0 + py + r) * W + x0 + px) = o;
        }
    }
}

// ---------------- conv3: 1x1, 64 -> 8, ReLU ----------------
__global__ void __launch_bounds__(256) k_conv3(const float* __restrict__ w3) {
    __shared__ float sW[512];
    int t = threadIdx.x;
    for (int i = t; i < 512; i += 256) sW[i] = w3[i];
    __syncthreads();

    int idx = blockIdx.x * 256 + t;
    int pix = idx * 4;
    int n = pix / HW;
    int p = pix % HW;

    float acc[8][4];
    #pragma unroll
    for (int co = 0; co < 8; co++) { acc[co][0]=0.f; acc[co][1]=0.f; acc[co][2]=0.f; acc[co][3]=0.f; }

    const float* base = g_x2 + (size_t)(n*64) * HW + p;
    #pragma unroll 4
    for (int ci = 0; ci < 64; ci++) {
        float4 v = *reinterpret_cast<const float4*>(base + (size_t)ci * HW);
        #pragma unroll
        for (int co = 0; co < 8; co++) {
            float wv = sW[co*64 + ci];
            acc[co][0] = fmaf(wv, v.x, acc[co][0]);
            acc[co][1] = fmaf(wv, v.y, acc[co][1]);
            acc[co][2] = fmaf(wv, v.z, acc[co][2]);
            acc[co][3] = fmaf(wv, v.w, acc[co][3]);
        }
    }
    #pragma unroll
    for (int co = 0; co < 8; co++) {
        float4 o = make_float4(fmaxf(acc[co][0], 0.f), fmaxf(acc[co][1], 0.f),
                               fmaxf(acc[co][2], 0.f), fmaxf(acc[co][3], 0.f));
        *reinterpret_cast<float4*>(g_aff + (size_t)(n*8 + co) * HW + p) = o;
    }
}

// ---------------- softmax propagation + blend ----------------
__global__ void k_prop(const float* __restrict__ disp, float* __restrict__ out) {
    int idx = blockIdx.x * blockDim.x + threadIdx.x;
    if (idx >= NB*HW) return;
    int x = idx & 255;
    int y = (idx >> 8) & 255;
    int n = idx >> 16;

    const int dy[8] = { 1, 1, 1, 0, 0, -1, -1, -1 };
    const int dx[8] = { 1, 0,-1, 1,-1,  1,  0, -1 };

    float g[8], dd[8];
    #pragma unroll
    for (int k = 0; k < 8; k++) {
        int yy = y + dy[k], xx = x + dx[k];
        bool ok = (yy >= 0 && yy < H && xx >= 0 && xx < W);
        g[k]  = ok ? g_aff[((size_t)(n*8 + k) * H + yy) * W + xx] : 0.f;
        dd[k] = ok ? disp[((size_t)n * H + yy) * W + xx] : 0.f;
    }
    float m = g[0];
    #pragma unroll
    for (int k = 1; k < 8; k++) m = fmaxf(m, g[k]);
    float se = 0.f, sp = 0.f;
    #pragma unroll
    for (int k = 0; k < 8; k++) {
        float e = expf(g[k] - m);
        se += e;
        sp = fmaf(e, dd[k], sp);
    }
    float prop = sp / se;
    out[idx] = 0.3f * prop + 0.7f * disp[idx];
}

// ---------------- launch ----------------
extern "C" void kernel_launch(void* const* d_in, const int* in_sizes, int n_in,
                              void* d_out, int out_size) {
    const float* normal = (const float*)d_in[0];
    const float* left   = (const float*)d_in[1];
    const float* right  = (const float*)d_in[2];
    const float* disp   = (const float*)d_in[3];
    const float* w1 = (const float*)d_in[4];
    const float* g1 = (const float*)d_in[5];
    const float* b1 = (const float*)d_in[6];
    const float* m1 = (const float*)d_in[7];
    const float* v1 = (const float*)d_in[8];
    const float* w2 = (const float*)d_in[9];
    const float* g2 = (const float*)d_in[10];
    const float* b2 = (const float*)d_in[11];
    const float* m2 = (const float*)d_in[12];
    const float* v2 = (const float*)d_in[13];
    const float* w3 = (const float*)d_in[14];
    float* out = (float*)d_out;

    k_bnfold<<<1, 64>>>(g1, b1, m1, v1, g2, b2, m2, v2);

    int total3 = NB*3*HW;
    k_resize_right<<<(total3 + 255) / 256, 256>>>(right);
    k_feats<<<(total3 + 255) / 256, 256>>>(left, normal, disp);

    k_conv1<<<dim3(4, 16, NB*4), 128>>>(w1);
    k_conv2<<<dim3(4, 16, NB*8), 128>>>(w2);
    k_conv3<<<(NB*HW/4 + 255) / 256, 256>>>(w3);

    k_prop<<<(NB*HW + 255) / 256, 256>>>(disp, out);
}

// round 4
// speedup vs baseline: 2.1096x; 2.1096x over previous
#include <cuda_runtime.h>
#include <math.h>

#define NB 8
#define H 256
#define W 256
#define H2 512
#define W2 512
#define HW (H*W)

// ---------------- scratch (device globals; no allocation) ----------------
__device__ float g_curr[NB*3*HW];    // resized right image
__device__ float g_feats[NB*12*HW];  // concat features
__device__ float g_x1[NB*32*HW];     // conv1 out (tf32-rounded values)
__device__ float g_x2[NB*64*HW];     // conv2 out
__device__ float g_aff[NB*8*HW];     // conv3 out (affinities)
__device__ float g_s1[32], g_bb1[32], g_s2[64], g_bb2[64]; // folded BN
__device__ unsigned int g_wt2[4*9*4*16*8];  // conv2 weights, tf32 bits, frag-ordered

__device__ __forceinline__ unsigned int f2tf32(float v) {
    unsigned int r; asm("cvt.rna.tf32.f32 %0, %1;" : "=r"(r) : "f"(v)); return r;
}

// ---------------- BN fold ----------------
__global__ void k_bnfold(const float* __restrict__ g1, const float* __restrict__ b1,
                         const float* __restrict__ m1, const float* __restrict__ v1,
                         const float* __restrict__ g2, const float* __restrict__ b2,
                         const float* __restrict__ m2, const float* __restrict__ v2) {
    int i = threadIdx.x;
    if (i < 32) { float s = g1[i] * rsqrtf(v1[i] + 1e-5f); g_s1[i] = s; g_bb1[i] = b1[i] - m1[i] * s; }
    if (i < 64) { float s = g2[i] * rsqrtf(v2[i] + 1e-5f); g_s2[i] = s; g_bb2[i] = b2[i] - m2[i] * s; }
}

// ---------------- conv2 weight prep: OIHW -> [m][p][cc][r][k] tf32 bits ----------------
__global__ void k_wprep(const float* __restrict__ w2) {
    int idx = blockIdx.x * blockDim.x + threadIdx.x;   // 64*32*9 = 18432
    if (idx >= 64*32*9) return;
    int p  = idx % 9;
    int ci = (idx / 9) % 32;
    int co = idx / (9*32);
    int m = co >> 4, r = co & 15;
    int cc = ci >> 3, k = ci & 7;
    int dst = (((m*9 + p)*4 + cc)*16 + r)*8 + k;
    g_wt2[dst] = f2tf32(w2[(size_t)co*288 + ci*9 + p]);
}

// ---------------- resize right (2x2 avg pool) ----------------
__global__ void k_resize_right(const float* __restrict__ right) {
    int idx = blockIdx.x * blockDim.x + threadIdx.x;
    if (idx >= NB*3*HW) return;
    int x = idx & 255;
    int y = (idx >> 8) & 255;
    int nc = idx >> 16;
    int c = nc % 3, n = nc / 3;
    const float* src = right + ((size_t)(n*3 + c) * H2 + 2*y) * W2 + 2*x;
    float v = 0.25f * (src[0] + src[1] + src[W2] + src[W2+1]);
    g_curr[idx] = v;
    g_feats[((size_t)(n*12 + 6 + c) * H + y) * W + x] = v;
}

// ---------------- left resize + normal copy + LR-warp error ----------------
__global__ void k_feats(const float* __restrict__ left, const float* __restrict__ normal,
                        const float* __restrict__ disp) {
    int idx = blockIdx.x * blockDim.x + threadIdx.x;
    if (idx >= NB*3*HW) return;
    int x = idx & 255;
    int y = (idx >> 8) & 255;
    int nc = idx >> 16;
    int c = nc % 3, n = nc / 3;

    const float* srcL = left + ((size_t)(n*3 + c) * H2 + 2*y) * W2 + 2*x;
    float l = 0.25f * (srcL[0] + srcL[1] + srcL[W2] + srcL[W2+1]);

    size_t base = ((size_t)(n*12) * H + y) * W + x;
    g_feats[base + (size_t)c * HW]     = normal[((size_t)(n*3 + c) * H + y) * W + x];
    g_feats[base + (size_t)(3+c) * HW] = l;

    float d = disp[((size_t)n * H + y) * W + x];
    float xs = (float)x - d;
    float x0f = floorf(xs);
    float frac = xs - x0f;
    int x0i = (int)x0f;
    int x1i = x0i + 1;
    float v0 = (x0i >= 0 && x0i < W) ? 1.f : 0.f;
    float v1 = (x1i >= 0 && x1i < W) ? 1.f : 0.f;
    int x0c = min(max(x0i, 0), W-1);
    int x1c = min(max(x1i, 0), W-1);
    const float* r = g_curr + ((size_t)(n*3 + c) * H + y) * W;
    float warped = (r[x0c] * v0) * (1.f - frac) + (r[x1c] * v1) * frac;
    g_feats[base + (size_t)(9+c) * HW] = fabsf(l - warped);
}

// ---------------- conv1: 12 -> 32, 3x3, pad 1, BN+ReLU (scalar, R1 scheme) ----------------
// block 256 thr, tile 32x32 pixels, 8 out-channels per block. Output tf32-rounded.
__global__ void __launch_bounds__(256) k_conv1(const float* __restrict__ w) {
    __shared__ float sIn[6][34][34];
    __shared__ float sW[8*12*9];
    int t = threadIdx.x;
    int bz = blockIdx.z;
    int n = bz >> 2, cg = bz & 3;
    int x0 = blockIdx.x * 32, y0 = blockIdx.y * 32;

    for (int i = t; i < 8*12*9; i += 256) sW[i] = w[cg*8*108 + i];

    float acc[8][4];
    #pragma unroll
    for (int co = 0; co < 8; co++) { acc[co][0]=0.f; acc[co][1]=0.f; acc[co][2]=0.f; acc[co][3]=0.f; }

    int tx = t & 15, ty = t >> 4;
    int px = tx * 2, py = ty * 2;

    for (int cc = 0; cc < 2; cc++) {
        __syncthreads();
        for (int i = t; i < 6*34*34; i += 256) {
            int ci = i / 1156; int rem = i % 1156;
            int yy = rem / 34, xx = rem % 34;
            int gy = y0 + yy - 1, gx = x0 + xx - 1;
            float v = 0.f;
            if ((unsigned)gy < H && (unsigned)gx < W)
                v = g_feats[((size_t)(n*12 + cc*6 + ci) * H + gy) * W + gx];
            sIn[ci][yy][xx] = v;
        }
        __syncthreads();
        for (int ci = 0; ci < 6; ci++) {
            float r[4][4];
            #pragma unroll
            for (int i = 0; i < 4; i++)
                #pragma unroll
                for (int j = 0; j < 4; j++)
                    r[i][j] = sIn[ci][py+i][px+j];
            #pragma unroll
            for (int co = 0; co < 8; co++) {
                const float* wp = &sW[(co*12 + cc*6 + ci) * 9];
                #pragma unroll
                for (int ky = 0; ky < 3; ky++)
                    #pragma unroll
                    for (int kx = 0; kx < 3; kx++) {
                        float wv = wp[ky*3 + kx];
                        acc[co][0] = fmaf(wv, r[ky  ][kx  ], acc[co][0]);
                        acc[co][1] = fmaf(wv, r[ky  ][kx+1], acc[co][1]);
                        acc[co][2] = fmaf(wv, r[ky+1][kx  ], acc[co][2]);
                        acc[co][3] = fmaf(wv, r[ky+1][kx+1], acc[co][3]);
                    }
            }
        }
    }

    #pragma unroll
    for (int co = 0; co < 8; co++) {
        int oc = cg*8 + co;
        float s = g_s1[oc], bo = g_bb1[oc];
        float* o = g_x1 + ((size_t)(n*32 + oc) * H + y0 + py) * W + x0 + px;
        // BN + ReLU, then round to tf32 so conv2's MMA operand is pre-rounded
        float a0 = fmaxf(fmaf(acc[co][0], s, bo), 0.f);
        float a1 = fmaxf(fmaf(acc[co][1], s, bo), 0.f);
        float a2 = fmaxf(fmaf(acc[co][2], s, bo), 0.f);
        float a3 = fmaxf(fmaf(acc[co][3], s, bo), 0.f);
        float2 top = make_float2(__uint_as_float(f2tf32(a0)), __uint_as_float(f2tf32(a1)));
        float2 bot = make_float2(__uint_as_float(f2tf32(a2)), __uint_as_float(f2tf32(a3)));
        *reinterpret_cast<float2*>(o)     = top;
        *reinterpret_cast<float2*>(o + W) = bot;
    }
}

// ================= conv2: 32 -> 64, 3x3, pad 1, BN+ReLU — TF32 MMA =================
// block 256 thr = 8 warps: 4 M-warps (16 couts each) x 2 N-warps (32 pixels each).
// Output tile: 64 couts x 64 pixels (one row chunk). K = 9 pos x 4 cin-chunks of 8.
// grid (W/64, H, NB)
__global__ void __launch_bounds__(256) k_conv2(const float* __restrict__ w_unused) {
    __shared__ float sB[8][3][72];   // [ci-in-chunk][row ky][x halo 0..65, pad 72]
    int t = threadIdx.x;
    int warp = t >> 5, lane = t & 31;
    int mw = warp & 3;          // M-warp: couts mw*16..mw*16+15
    int nw = warp >> 2;         // N-warp: pixels nw*32..nw*32+31
    int g = lane >> 2, t4 = lane & 3;

    int x0 = blockIdx.x * 64;
    int y  = blockIdx.y;
    int n  = blockIdx.z;

    float c[4][4];               // [n-tile][c0..c3]
    #pragma unroll
    for (int nt = 0; nt < 4; nt++) { c[nt][0]=0.f; c[nt][1]=0.f; c[nt][2]=0.f; c[nt][3]=0.f; }

    for (int cc = 0; cc < 4; cc++) {
        __syncthreads();
        // fill sB: 8 ci x 3 rows x 66 cols
        for (int i = t; i < 8*3*66; i += 256) {
            int ci = i / 198; int rem = i - ci*198;
            int r = rem / 66, xx = rem - r*66;
            int gy = y + r - 1, gx = x0 + xx - 1;
            float v = 0.f;
            if ((unsigned)gy < H && (unsigned)gx < W)
                v = g_x1[((size_t)(n*32 + cc*8 + ci) * H + gy) * W + gx];
            sB[ci][r][xx] = v;
        }
        __syncthreads();

        #pragma unroll
        for (int ky = 0; ky < 3; ky++) {
            #pragma unroll
            for (int kx = 0; kx < 3; kx++) {
                int p = ky*3 + kx;
                // A fragment from frag-ordered global weights (L1-resident)
                int off = (((mw*9 + p)*4 + cc)*16)*8 + g*8 + t4;
                unsigned int a0 = g_wt2[off];
                unsigned int a1 = g_wt2[off + 64];   // (g+8)*8
                unsigned int a2 = g_wt2[off + 4];
                unsigned int a3 = g_wt2[off + 68];
                const float* bb = &sB[t4][ky][nw*32 + g + kx];
                #pragma unroll
                for (int nt = 0; nt < 4; nt++) {
                    unsigned int b0 = __float_as_uint(bb[nt*8]);
                    unsigned int b1 = __float_as_uint(bb[nt*8 + 864]);  // ci +4
                    asm volatile(
                        "mma.sync.aligned.m16n8k8.row.col.f32.tf32.tf32.f32 "
                        "{%0,%1,%2,%3}, {%4,%5,%6,%7}, {%8,%9}, {%0,%1,%2,%3};\n"
                        : "+f"(c[nt][0]), "+f"(c[nt][1]), "+f"(c[nt][2]), "+f"(c[nt][3])
                        : "r"(a0), "r"(a1), "r"(a2), "r"(a3), "r"(b0), "r"(b1));
                }
            }
        }
    }

    // epilogue: BN + ReLU, store
    int co0 = mw*16 + g;
    int co1 = co0 + 8;
    float s0 = g_s2[co0], bo0 = g_bb2[co0];
    float s1 = g_s2[co1], bo1 = g_bb2[co1];
    #pragma unroll
    for (int nt = 0; nt < 4; nt++) {
        int x = x0 + nw*32 + nt*8 + 2*t4;
        float2 o0 = make_float2(fmaxf(fmaf(c[nt][0], s0, bo0), 0.f),
                                fmaxf(fmaf(c[nt][1], s0, bo0), 0.f));
        float2 o1 = make_float2(fmaxf(fmaf(c[nt][2], s1, bo1), 0.f),
                                fmaxf(fmaf(c[nt][3], s1, bo1), 0.f));
        *reinterpret_cast<float2*>(g_x2 + ((size_t)(n*64 + co0) * H + y) * W + x) = o0;
        *reinterpret_cast<float2*>(g_x2 + ((size_t)(n*64 + co1) * H + y) * W + x) = o1;
    }
}

// ---------------- conv3: 1x1, 64 -> 8, ReLU ----------------
__global__ void __launch_bounds__(256) k_conv3(const float* __restrict__ w3) {
    __shared__ float sW[512];
    int t = threadIdx.x;
    for (int i = t; i < 512; i += 256) sW[i] = w3[i];
    __syncthreads();

    int idx = blockIdx.x * 256 + t;
    int pix = idx * 4;
    int n = pix / HW;
    int p = pix % HW;

    float acc[8][4];
    #pragma unroll
    for (int co = 0; co < 8; co++) { acc[co][0]=0.f; acc[co][1]=0.f; acc[co][2]=0.f; acc[co][3]=0.f; }

    const float* base = g_x2 + (size_t)(n*64) * HW + p;
    #pragma unroll 4
    for (int ci = 0; ci < 64; ci++) {
        float4 v = *reinterpret_cast<const float4*>(base + (size_t)ci * HW);
        #pragma unroll
        for (int co = 0; co < 8; co++) {
            float wv = sW[co*64 + ci];
            acc[co][0] = fmaf(wv, v.x, acc[co][0]);
            acc[co][1] = fmaf(wv, v.y, acc[co][1]);
            acc[co][2] = fmaf(wv, v.z, acc[co][2]);
            acc[co][3] = fmaf(wv, v.w, acc[co][3]);
        }
    }
    #pragma unroll
    for (int co = 0; co < 8; co++) {
        float4 o = make_float4(fmaxf(acc[co][0], 0.f), fmaxf(acc[co][1], 0.f),
                               fmaxf(acc[co][2], 0.f), fmaxf(acc[co][3], 0.f));
        *reinterpret_cast<float4*>(g_aff + (size_t)(n*8 + co) * HW + p) = o;
    }
}

// ---------------- softmax propagation + blend ----------------
__global__ void k_prop(const float* __restrict__ disp, float* __restrict__ out) {
    int idx = blockIdx.x * blockDim.x + threadIdx.x;
    if (idx >= NB*HW) return;
    int x = idx & 255;
    int y = (idx >> 8) & 255;
    int n = idx >> 16;

    const int dy[8] = { 1, 1, 1, 0, 0, -1, -1, -1 };
    const int dx[8] = { 1, 0,-1, 1,-1,  1,  0, -1 };

    float g[8], dd[8];
    #pragma unroll
    for (int k = 0; k < 8; k++) {
        int yy = y + dy[k], xx = x + dx[k];
        bool ok = (yy >= 0 && yy < H && xx >= 0 && xx < W);
        g[k]  = ok ? g_aff[((size_t)(n*8 + k) * H + yy) * W + xx] : 0.f;
        dd[k] = ok ? disp[((size_t)n * H + yy) * W + xx] : 0.f;
    }
    float m = g[0];
    #pragma unroll
    for (int k = 1; k < 8; k++) m = fmaxf(m, g[k]);
    float se = 0.f, sp = 0.f;
    #pragma unroll
    for (int k = 0; k < 8; k++) {
        float e = expf(g[k] - m);
        se += e;
        sp = fmaf(e, dd[k], sp);
    }
    float prop = sp / se;
    out[idx] = 0.3f * prop + 0.7f * disp[idx];
}

// ---------------- launch ----------------
extern "C" void kernel_launch(void* const* d_in, const int* in_sizes, int n_in,
                              void* d_out, int out_size) {
    const float* normal = (const float*)d_in[0];
    const float* left   = (const float*)d_in[1];
    const float* right  = (const float*)d_in[2];
    const float* disp   = (const float*)d_in[3];
    const float* w1 = (const float*)d_in[4];
    const float* g1 = (const float*)d_in[5];
    const float* b1 = (const float*)d_in[6];
    const float* m1 = (const float*)d_in[7];
    const float* v1 = (const float*)d_in[8];
    const float* w2 = (const float*)d_in[9];
    const float* g2 = (const float*)d_in[10];
    const float* b2 = (const float*)d_in[11];
    const float* m2 = (const float*)d_in[12];
    const float* v2 = (const float*)d_in[13];
    const float* w3 = (const float*)d_in[14];
    float* out = (float*)d_out;

    k_bnfold<<<1, 64>>>(g1, b1, m1, v1, g2, b2, m2, v2);
    k_wprep<<<(64*32*9 + 255) / 256, 256>>>(w2);

    int total3 = NB*3*HW;
    k_resize_right<<<(total3 + 255) / 256, 256>>>(right);
    k_feats<<<(total3 + 255) / 256, 256>>>(left, normal, disp);

    k_conv1<<<dim3(8, 8, NB*4), 256>>>(w1);
    k_conv2<<<dim3(W/64, H, NB), 256>>>(w2);
    k_conv3<<<(NB*HW/4 + 255) / 256, 256>>>(w3);

    k_prop<<<(NB*HW + 255) / 256, 256>>>(disp, out);
}

// round 5
// speedup vs baseline: 2.5174x; 1.1933x over previous
#include <cuda_runtime.h>
#include <math.h>

#define NB 8
#define H 256
#define W 256
#define H2 512
#define W2 512
#define HW (H*W)

// ---------------- scratch (device globals; no allocation) ----------------
__device__ float g_curr[NB*3*HW];      // resized right image
__device__ float g_featsP[NB*16*HW];   // concat features, padded to 16 ch (12..15 stay zero)
__device__ float g_x1[NB*32*HW];       // conv1 out (tf32-rounded values)
__device__ float g_x2[NB*64*HW];       // conv2 out
__device__ float g_aff[NB*8*HW];       // conv3 out (affinities)
__device__ float g_s1[32], g_bb1[32], g_s2[64], g_bb2[64]; // folded BN
__device__ unsigned int g_wt1[2*9*2*16*8];  // conv1 weights, tf32, frag-ordered (ci padded to 16)
__device__ unsigned int g_wt2[4*9*4*16*8];  // conv2 weights, tf32, frag-ordered

__device__ __forceinline__ unsigned int f2tf32(float v) {
    unsigned int r; asm("cvt.rna.tf32.f32 %0, %1;" : "=r"(r) : "f"(v)); return r;
}
__device__ __forceinline__ float tf32r(float v) { return __uint_as_float(f2tf32(v)); }

// ---------------- BN fold ----------------
__global__ void k_bnfold(const float* __restrict__ g1, const float* __restrict__ b1,
                         const float* __restrict__ m1, const float* __restrict__ v1,
                         const float* __restrict__ g2, const float* __restrict__ b2,
                         const float* __restrict__ m2, const float* __restrict__ v2) {
    int i = threadIdx.x;
    if (i < 32) { float s = g1[i] * rsqrtf(v1[i] + 1e-5f); g_s1[i] = s; g_bb1[i] = b1[i] - m1[i] * s; }
    if (i < 64) { float s = g2[i] * rsqrtf(v2[i] + 1e-5f); g_s2[i] = s; g_bb2[i] = b2[i] - m2[i] * s; }
}

// ---------------- weight prep ----------------
// conv1: (32,12,3,3) -> [m(2)][p(9)][cc(2)][r(16)][k(8)] tf32 (padded ci entries never written -> 0)
__global__ void k_wprep1(const float* __restrict__ w1) {
    int idx = blockIdx.x * blockDim.x + threadIdx.x;   // 32*12*9 = 3456
    if (idx >= 32*12*9) return;
    int p  = idx % 9;
    int ci = (idx / 9) % 12;
    int co = idx / (9*12);
    int m = co >> 4, r = co & 15;
    int cc = ci >> 3, k = ci & 7;
    int dst = (((m*9 + p)*2 + cc)*16 + r)*8 + k;
    g_wt1[dst] = f2tf32(w1[(size_t)co*108 + ci*9 + p]);
}
// conv2: (64,32,3,3) -> [m(4)][p(9)][cc(4)][r(16)][k(8)]
__global__ void k_wprep2(const float* __restrict__ w2) {
    int idx = blockIdx.x * blockDim.x + threadIdx.x;   // 64*32*9 = 18432
    if (idx >= 64*32*9) return;
    int p  = idx % 9;
    int ci = (idx / 9) % 32;
    int co = idx / (9*32);
    int m = co >> 4, r = co & 15;
    int cc = ci >> 3, k = ci & 7;
    int dst = (((m*9 + p)*4 + cc)*16 + r)*8 + k;
    g_wt2[dst] = f2tf32(w2[(size_t)co*288 + ci*9 + p]);
}

// ---------------- resize right (2x2 avg pool) ----------------
__global__ void k_resize_right(const float* __restrict__ right) {
    int idx = blockIdx.x * blockDim.x + threadIdx.x;
    if (idx >= NB*3*HW) return;
    int x = idx & 255;
    int y = (idx >> 8) & 255;
    int nc = idx >> 16;
    int c = nc % 3, n = nc / 3;
    const float* src = right + ((size_t)(n*3 + c) * H2 + 2*y) * W2 + 2*x;
    float v = 0.25f * (src[0] + src[1] + src[W2] + src[W2+1]);
    g_curr[idx] = v;
    g_featsP[((size_t)(n*16 + 6 + c) * H + y) * W + x] = tf32r(v);
}

// ---------------- left resize + normal copy + LR-warp error ----------------
__global__ void k_feats(const float* __restrict__ left, const float* __restrict__ normal,
                        const float* __restrict__ disp) {
    int idx = blockIdx.x * blockDim.x + threadIdx.x;
    if (idx >= NB*3*HW) return;
    int x = idx & 255;
    int y = (idx >> 8) & 255;
    int nc = idx >> 16;
    int c = nc % 3, n = nc / 3;

    const float* srcL = left + ((size_t)(n*3 + c) * H2 + 2*y) * W2 + 2*x;
    float l = 0.25f * (srcL[0] + srcL[1] + srcL[W2] + srcL[W2+1]);

    size_t base = ((size_t)(n*16) * H + y) * W + x;
    g_featsP[base + (size_t)c * HW]     = tf32r(normal[((size_t)(n*3 + c) * H + y) * W + x]);
    g_featsP[base + (size_t)(3+c) * HW] = tf32r(l);

    float d = disp[((size_t)n * H + y) * W + x];
    float xs = (float)x - d;
    float x0f = floorf(xs);
    float frac = xs - x0f;
    int x0i = (int)x0f;
    int x1i = x0i + 1;
    float v0 = (x0i >= 0 && x0i < W) ? 1.f : 0.f;
    float v1 = (x1i >= 0 && x1i < W) ? 1.f : 0.f;
    int x0c = min(max(x0i, 0), W-1);
    int x1c = min(max(x1i, 0), W-1);
    const float* r = g_curr + ((size_t)(n*3 + c) * H + y) * W;
    float warped = (r[x0c] * v0) * (1.f - frac) + (r[x1c] * v1) * frac;
    g_featsP[base + (size_t)(9+c) * HW] = tf32r(fabsf(l - warped));
}

// ================= conv1: 16(pad) -> 32, 3x3, pad 1, BN+ReLU — TF32 MMA =================
// block 256 = 8 warps: 2 M-warps (16 couts) x 4 N-warps (32 px). Tile: 32 couts x 128 px x 2 rows.
// grid (W/128, H/2, NB). K = 9 pos x 2 cin-chunks of 8.
__global__ void __launch_bounds__(256) k_conv1(const float* __restrict__ w_unused) {
    __shared__ float sB[8][4][138];   // [ci][row y0-1..y0+2][x halo 0..129], stride 138 (banks ok)
    int t = threadIdx.x;
    int warp = t >> 5, lane = t & 31;
    int mw = warp & 1;          // couts mw*16..+15
    int nw = warp >> 1;         // pixels nw*32..+31
    int g = lane >> 2, t4 = lane & 3;

    int x0 = blockIdx.x * 128;
    int y0 = blockIdx.y * 2;
    int n  = blockIdx.z;

    float c[2][4][4];           // [row][n-tile][acc]
    #pragma unroll
    for (int r = 0; r < 2; r++)
        #pragma unroll
        for (int nt = 0; nt < 4; nt++) { c[r][nt][0]=0.f; c[r][nt][1]=0.f; c[r][nt][2]=0.f; c[r][nt][3]=0.f; }

    for (int cc = 0; cc < 2; cc++) {
        __syncthreads();
        // fill sB: 8 ci x 4 rows x 130 cols
        for (int i = t; i < 8*4*130; i += 256) {
            int ci = i / 520; int rem = i - ci*520;
            int r = rem / 130, xx = rem - r*130;
            int gy = y0 + r - 1, gx = x0 + xx - 1;
            float v = 0.f;
            if ((unsigned)gy < H && (unsigned)gx < W)
                v = g_featsP[((size_t)(n*16 + cc*8 + ci) * H + gy) * W + gx];
            sB[ci][r][xx] = v;
        }
        __syncthreads();

        #pragma unroll
        for (int ky = 0; ky < 3; ky++) {
            #pragma unroll
            for (int kx = 0; kx < 3; kx++) {
                int p = ky*3 + kx;
                int off = (((mw*9 + p)*2 + cc)*16)*8 + g*8 + t4;
                unsigned int a0 = g_wt1[off];
                unsigned int a1 = g_wt1[off + 64];
                unsigned int a2 = g_wt1[off + 4];
                unsigned int a3 = g_wt1[off + 68];
                #pragma unroll
                for (int r = 0; r < 2; r++) {
                    const float* bb = &sB[t4][ky + r][nw*32 + g + kx];
                    #pragma unroll
                    for (int nt = 0; nt < 4; nt++) {
                        unsigned int b0 = __float_as_uint(bb[nt*8]);
                        unsigned int b1 = __float_as_uint(bb[nt*8 + 4*4*138]);  // ci +4
                        asm volatile(
                            "mma.sync.aligned.m16n8k8.row.col.f32.tf32.tf32.f32 "
                            "{%0,%1,%2,%3}, {%4,%5,%6,%7}, {%8,%9}, {%0,%1,%2,%3};\n"
                            : "+f"(c[r][nt][0]), "+f"(c[r][nt][1]), "+f"(c[r][nt][2]), "+f"(c[r][nt][3])
                            : "r"(a0), "r"(a1), "r"(a2), "r"(a3), "r"(b0), "r"(b1));
                    }
                }
            }
        }
    }

    int co0 = mw*16 + g;
    int co1 = co0 + 8;
    float s0 = g_s1[co0], bo0 = g_bb1[co0];
    float s1 = g_s1[co1], bo1 = g_bb1[co1];
    #pragma unroll
    for (int r = 0; r < 2; r++) {
        #pragma unroll
        for (int nt = 0; nt < 4; nt++) {
            int x = x0 + nw*32 + nt*8 + 2*t4;
            float2 o0 = make_float2(tf32r(fmaxf(fmaf(c[r][nt][0], s0, bo0), 0.f)),
                                    tf32r(fmaxf(fmaf(c[r][nt][1], s0, bo0), 0.f)));
            float2 o1 = make_float2(tf32r(fmaxf(fmaf(c[r][nt][2], s1, bo1), 0.f)),
                                    tf32r(fmaxf(fmaf(c[r][nt][3], s1, bo1), 0.f)));
            *reinterpret_cast<float2*>(g_x1 + ((size_t)(n*32 + co0) * H + y0 + r) * W + x) = o0;
            *reinterpret_cast<float2*>(g_x1 + ((size_t)(n*32 + co1) * H + y0 + r) * W + x) = o1;
        }
    }
}

// ================= conv2: 32 -> 64, 3x3, pad 1, BN+ReLU — TF32 MMA =================
// block 256 thr = 8 warps: 4 M-warps (16 couts each) x 2 N-warps (32 pixels each).
// Output tile: 64 couts x 64 pixels (one row chunk). K = 9 pos x 4 cin-chunks of 8.
// grid (W/64, H, NB)
__global__ void __launch_bounds__(256) k_conv2(const float* __restrict__ w_unused) {
    __shared__ float sB[8][3][72];   // [ci][row ky][x halo 0..65, pad 72]
    int t = threadIdx.x;
    int warp = t >> 5, lane = t & 31;
    int mw = warp & 3;
    int nw = warp >> 2;
    int g = lane >> 2, t4 = lane & 3;

    int x0 = blockIdx.x * 64;
    int y  = blockIdx.y;
    int n  = blockIdx.z;

    float c[4][4];
    #pragma unroll
    for (int nt = 0; nt < 4; nt++) { c[nt][0]=0.f; c[nt][1]=0.f; c[nt][2]=0.f; c[nt][3]=0.f; }

    for (int cc = 0; cc < 4; cc++) {
        __syncthreads();
        for (int i = t; i < 8*3*66; i += 256) {
            int ci = i / 198; int rem = i - ci*198;
            int r = rem / 66, xx = rem - r*66;
            int gy = y + r - 1, gx = x0 + xx - 1;
            float v = 0.f;
            if ((unsigned)gy < H && (unsigned)gx < W)
                v = g_x1[((size_t)(n*32 + cc*8 + ci) * H + gy) * W + gx];
            sB[ci][r][xx] = v;
        }
        __syncthreads();

        #pragma unroll
        for (int ky = 0; ky < 3; ky++) {
            #pragma unroll
            for (int kx = 0; kx < 3; kx++) {
                int p = ky*3 + kx;
                int off = (((mw*9 + p)*4 + cc)*16)*8 + g*8 + t4;
                unsigned int a0 = g_wt2[off];
                unsigned int a1 = g_wt2[off + 64];
                unsigned int a2 = g_wt2[off + 4];
                unsigned int a3 = g_wt2[off + 68];
                const float* bb = &sB[t4][ky][nw*32 + g + kx];
                #pragma unroll
                for (int nt = 0; nt < 4; nt++) {
                    unsigned int b0 = __float_as_uint(bb[nt*8]);
                    unsigned int b1 = __float_as_uint(bb[nt*8 + 864]);
                    asm volatile(
                        "mma.sync.aligned.m16n8k8.row.col.f32.tf32.tf32.f32 "
                        "{%0,%1,%2,%3}, {%4,%5,%6,%7}, {%8,%9}, {%0,%1,%2,%3};\n"
                        : "+f"(c[nt][0]), "+f"(c[nt][1]), "+f"(c[nt][2]), "+f"(c[nt][3])
                        : "r"(a0), "r"(a1), "r"(a2), "r"(a3), "r"(b0), "r"(b1));
                }
            }
        }
    }

    int co0 = mw*16 + g;
    int co1 = co0 + 8;
    float s0 = g_s2[co0], bo0 = g_bb2[co0];
    float s1 = g_s2[co1], bo1 = g_bb2[co1];
    #pragma unroll
    for (int nt = 0; nt < 4; nt++) {
        int x = x0 + nw*32 + nt*8 + 2*t4;
        float2 o0 = make_float2(fmaxf(fmaf(c[nt][0], s0, bo0), 0.f),
                                fmaxf(fmaf(c[nt][1], s0, bo0), 0.f));
        float2 o1 = make_float2(fmaxf(fmaf(c[nt][2], s1, bo1), 0.f),
                                fmaxf(fmaf(c[nt][3], s1, bo1), 0.f));
        *reinterpret_cast<float2*>(g_x2 + ((size_t)(n*64 + co0) * H + y) * W + x) = o0;
        *reinterpret_cast<float2*>(g_x2 + ((size_t)(n*64 + co1) * H + y) * W + x) = o1;
    }
}

// ---------------- conv3: 1x1, 64 -> 8, ReLU ----------------
__global__ void __launch_bounds__(256) k_conv3(const float* __restrict__ w3) {
    __shared__ float sW[512];
    int t = threadIdx.x;
    for (int i = t; i < 512; i += 256) sW[i] = w3[i];
    __syncthreads();

    int idx = blockIdx.x * 256 + t;
    int pix = idx * 4;
    int n = pix / HW;
    int p = pix % HW;

    float acc[8][4];
    #pragma unroll
    for (int co = 0; co < 8; co++) { acc[co][0]=0.f; acc[co][1]=0.f; acc[co][2]=0.f; acc[co][3]=0.f; }

    const float* base = g_x2 + (size_t)(n*64) * HW + p;
    #pragma unroll 4
    for (int ci = 0; ci < 64; ci++) {
        float4 v = *reinterpret_cast<const float4*>(base + (size_t)ci * HW);
        #pragma unroll
        for (int co = 0; co < 8; co++) {
            float wv = sW[co*64 + ci];
            acc[co][0] = fmaf(wv, v.x, acc[co][0]);
            acc[co][1] = fmaf(wv, v.y, acc[co][1]);
            acc[co][2] = fmaf(wv, v.z, acc[co][2]);
            acc[co][3] = fmaf(wv, v.w, acc[co][3]);
        }
    }
    #pragma unroll
    for (int co = 0; co < 8; co++) {
        float4 o = make_float4(fmaxf(acc[co][0], 0.f), fmaxf(acc[co][1], 0.f),
                               fmaxf(acc[co][2], 0.f), fmaxf(acc[co][3], 0.f));
        *reinterpret_cast<float4*>(g_aff + (size_t)(n*8 + co) * HW + p) = o;
    }
}

// ---------------- softmax propagation + blend ----------------
__global__ void k_prop(const float* __restrict__ disp, float* __restrict__ out) {
    int idx = blockIdx.x * blockDim.x + threadIdx.x;
    if (idx >= NB*HW) return;
    int x = idx & 255;
    int y = (idx >> 8) & 255;
    int n = idx >> 16;

    const int dy[8] = { 1, 1, 1, 0, 0, -1, -1, -1 };
    const int dx[8] = { 1, 0,-1, 1,-1,  1,  0, -1 };

    float g[8], dd[8];
    #pragma unroll
    for (int k = 0; k < 8; k++) {
        int yy = y + dy[k], xx = x + dx[k];
        bool ok = (yy >= 0 && yy < H && xx >= 0 && xx < W);
        g[k]  = ok ? g_aff[((size_t)(n*8 + k) * H + yy) * W + xx] : 0.f;
        dd[k] = ok ? disp[((size_t)n * H + yy) * W + xx] : 0.f;
    }
    float m = g[0];
    #pragma unroll
    for (int k = 1; k < 8; k++) m = fmaxf(m, g[k]);
    float se = 0.f, sp = 0.f;
    #pragma unroll
    for (int k = 0; k < 8; k++) {
        float e = expf(g[k] - m);
        se += e;
        sp = fmaf(e, dd[k], sp);
    }
    float prop = sp / se;
    out[idx] = 0.3f * prop + 0.7f * disp[idx];
}

// ---------------- launch ----------------
extern "C" void kernel_launch(void* const* d_in, const int* in_sizes, int n_in,
                              void* d_out, int out_size) {
    const float* normal = (const float*)d_in[0];
    const float* left   = (const float*)d_in[1];
    const float* right  = (const float*)d_in[2];
    const float* disp   = (const float*)d_in[3];
    const float* w1 = (const float*)d_in[4];
    const float* g1 = (const float*)d_in[5];
    const float* b1 = (const float*)d_in[6];
    const float* m1 = (const float*)d_in[7];
    const float* v1 = (const float*)d_in[8];
    const float* w2 = (const float*)d_in[9];
    const float* g2 = (const float*)d_in[10];
    const float* b2 = (const float*)d_in[11];
    const float* m2 = (const float*)d_in[12];
    const float* v2 = (const float*)d_in[13];
    const float* w3 = (const float*)d_in[14];
    float* out = (float*)d_out;

    k_bnfold<<<1, 64>>>(g1, b1, m1, v1, g2, b2, m2, v2);
    k_wprep1<<<(32*12*9 + 255) / 256, 256>>>(w1);
    k_wprep2<<<(64*32*9 + 255) / 256, 256>>>(w2);

    int total3 = NB*3*HW;
    k_resize_right<<<(total3 + 255) / 256, 256>>>(right);
    k_feats<<<(total3 + 255) / 256, 256>>>(left, normal, disp);

    k_conv1<<<dim3(W/128, H/2, NB), 256>>>(w1);
    k_conv2<<<dim3(W/64, H, NB), 256>>>(w2);
    k_conv3<<<(NB*HW/4 + 255) / 256, 256>>>(w3);

    k_prop<<<(NB*HW + 255) / 256, 256>>>(disp, out);
}

// round 6
// speedup vs baseline: 3.1182x; 1.2386x over previous
#include <cuda_runtime.h>
#include <math.h>

#define NB 8
#define H 256
#define W 256
#define H2 512
#define W2 512
#define HW (H*W)

// ---------------- scratch (device globals; no allocation) ----------------
__device__ float g_featsP[NB*16*HW];   // concat features, padded to 16 ch (12..15 stay zero)
__device__ float g_x1[NB*32*HW];       // conv1 out (tf32-rounded)
__device__ float g_x2[NB*64*HW];       // conv2 out
__device__ float g_s1[32], g_bb1[32], g_s2[64], g_bb2[64]; // folded BN
__device__ unsigned int g_wt1[2*9*2*16*8];  // conv1 weights, tf32, frag-ordered
__device__ unsigned int g_wt2[4*9*4*16*8];  // conv2 weights, tf32, frag-ordered

__device__ __forceinline__ unsigned int f2tf32(float v) {
    unsigned int r; asm("cvt.rna.tf32.f32 %0, %1;" : "=r"(r) : "f"(v)); return r;
}
__device__ __forceinline__ float tf32r(float v) { return __uint_as_float(f2tf32(v)); }

// ---------------- BN fold ----------------
__global__ void k_bnfold(const float* __restrict__ g1, const float* __restrict__ b1,
                         const float* __restrict__ m1, const float* __restrict__ v1,
                         const float* __restrict__ g2, const float* __restrict__ b2,
                         const float* __restrict__ m2, const float* __restrict__ v2) {
    int i = threadIdx.x;
    if (i < 32) { float s = g1[i] * rsqrtf(v1[i] + 1e-5f); g_s1[i] = s; g_bb1[i] = b1[i] - m1[i] * s; }
    if (i < 64) { float s = g2[i] * rsqrtf(v2[i] + 1e-5f); g_s2[i] = s; g_bb2[i] = b2[i] - m2[i] * s; }
}

// ---------------- weight prep ----------------
__global__ void k_wprep1(const float* __restrict__ w1) {
    int idx = blockIdx.x * blockDim.x + threadIdx.x;   // 32*12*9
    if (idx >= 32*12*9) return;
    int p  = idx % 9;
    int ci = (idx / 9) % 12;
    int co = idx / (9*12);
    int m = co >> 4, r = co & 15;
    int cc = ci >> 3, k = ci & 7;
    g_wt1[(((m*9 + p)*2 + cc)*16 + r)*8 + k] = f2tf32(w1[(size_t)co*108 + ci*9 + p]);
}
__global__ void k_wprep2(const float* __restrict__ w2) {
    int idx = blockIdx.x * blockDim.x + threadIdx.x;   // 64*32*9
    if (idx >= 64*32*9) return;
    int p  = idx % 9;
    int ci = (idx / 9) % 32;
    int co = idx / (9*32);
    int m = co >> 4, r = co & 15;
    int cc = ci >> 3, k = ci & 7;
    g_wt2[(((m*9 + p)*4 + cc)*16 + r)*8 + k] = f2tf32(w2[(size_t)co*288 + ci*9 + p]);
}

// ---------------- fused preprocessing: normal / resized-left / resized-right / warp error ----------------
__global__ void k_pre(const float* __restrict__ left, const float* __restrict__ right,
                      const float* __restrict__ normal, const float* __restrict__ disp) {
    int idx = blockIdx.x * blockDim.x + threadIdx.x;
    if (idx >= NB*3*HW) return;
    int x = idx & 255;
    int y = (idx >> 8) & 255;
    int nc = idx >> 16;
    int c = nc % 3, n = nc / 3;

    const float* rrow = right + ((size_t)(n*3 + c) * H2 + 2*y) * W2;
    float rv = 0.25f * (rrow[2*x] + rrow[2*x+1] + rrow[2*x+W2] + rrow[2*x+W2+1]);

    const float* srcL = left + ((size_t)(n*3 + c) * H2 + 2*y) * W2 + 2*x;
    float l = 0.25f * (srcL[0] + srcL[1] + srcL[W2] + srcL[W2+1]);

    size_t base = ((size_t)(n*16) * H + y) * W + x;
    g_featsP[base + (size_t)c * HW]     = tf32r(normal[((size_t)(n*3 + c) * H + y) * W + x]);
    g_featsP[base + (size_t)(3+c) * HW] = tf32r(l);
    g_featsP[base + (size_t)(6+c) * HW] = tf32r(rv);

    float d = disp[((size_t)n * H + y) * W + x];
    float xs = (float)x - d;
    float x0f = floorf(xs);
    float frac = xs - x0f;
    int x0i = (int)x0f;
    int x1i = x0i + 1;
    float v0 = (x0i >= 0 && x0i < W) ? 1.f : 0.f;
    float v1 = (x1i >= 0 && x1i < W) ? 1.f : 0.f;
    int x0c = min(max(x0i, 0), W-1);
    int x1c = min(max(x1i, 0), W-1);
    // resized-right value at gathered x positions, computed on the fly
    float r0 = 0.25f * (rrow[2*x0c] + rrow[2*x0c+1] + rrow[2*x0c+W2] + rrow[2*x0c+W2+1]);
    float r1 = 0.25f * (rrow[2*x1c] + rrow[2*x1c+1] + rrow[2*x1c+W2] + rrow[2*x1c+W2+1]);
    float warped = (r0 * v0) * (1.f - frac) + (r1 * v1) * frac;
    g_featsP[base + (size_t)(9+c) * HW] = tf32r(fabsf(l - warped));
}

// ================= conv1: 16(pad) -> 32, 3x3, pad 1, BN+ReLU — TF32 MMA =================
// block 256 = 2 M-warps x 4 N-warps. Tile: 32 couts x 128 px x 2 rows. Single-phase smem.
__global__ void __launch_bounds__(256) k_conv1(const float* __restrict__ w_unused) {
    __shared__ float sB[16][4][138];   // 35.3 KB; ci stride 552 ≡ 8 (mod 32) — conflict-free
    int t = threadIdx.x;
    int warp = t >> 5, lane = t & 31;
    int mw = warp & 1;
    int nw = warp >> 1;
    int g = lane >> 2, t4 = lane & 3;

    int x0 = blockIdx.x * 128;
    int y0 = blockIdx.y * 2;
    int n  = blockIdx.z;

    float c[2][4][4];
    #pragma unroll
    for (int r = 0; r < 2; r++)
        #pragma unroll
        for (int nt = 0; nt < 4; nt++) { c[r][nt][0]=0.f; c[r][nt][1]=0.f; c[r][nt][2]=0.f; c[r][nt][3]=0.f; }

    // single fill: all 16 ci x 4 rows x 130 cols
    for (int i = t; i < 16*4*130; i += 256) {
        int ci = i / 520; int rem = i - ci*520;
        int r = rem / 130, xx = rem - r*130;
        int gy = y0 + r - 1, gx = x0 + xx - 1;
        float v = 0.f;
        if ((unsigned)gy < H && (unsigned)gx < W)
            v = g_featsP[((size_t)(n*16 + ci) * H + gy) * W + gx];
        sB[ci][r][xx] = v;
    }
    __syncthreads();

    #pragma unroll
    for (int cc = 0; cc < 2; cc++) {
        #pragma unroll
        for (int ky = 0; ky < 3; ky++) {
            #pragma unroll
            for (int kx = 0; kx < 3; kx++) {
                int p = ky*3 + kx;
                int off = (((mw*9 + p)*2 + cc)*16)*8 + g*8 + t4;
                unsigned int a0 = g_wt1[off];
                unsigned int a1 = g_wt1[off + 64];
                unsigned int a2 = g_wt1[off + 4];
                unsigned int a3 = g_wt1[off + 68];
                #pragma unroll
                for (int r = 0; r < 2; r++) {
                    const float* bb = &sB[cc*8 + t4][ky + r][nw*32 + g + kx];
                    #pragma unroll
                    for (int nt = 0; nt < 4; nt++) {
                        unsigned int b0 = __float_as_uint(bb[nt*8]);
                        unsigned int b1 = __float_as_uint(bb[nt*8 + 4*4*138]);  // ci +4
                        asm volatile(
                            "mma.sync.aligned.m16n8k8.row.col.f32.tf32.tf32.f32 "
                            "{%0,%1,%2,%3}, {%4,%5,%6,%7}, {%8,%9}, {%0,%1,%2,%3};\n"
                            : "+f"(c[r][nt][0]), "+f"(c[r][nt][1]), "+f"(c[r][nt][2]), "+f"(c[r][nt][3])
                            : "r"(a0), "r"(a1), "r"(a2), "r"(a3), "r"(b0), "r"(b1));
                    }
                }
            }
        }
    }

    int co0 = mw*16 + g;
    int co1 = co0 + 8;
    float s0 = g_s1[co0], bo0 = g_bb1[co0];
    float s1 = g_s1[co1], bo1 = g_bb1[co1];
    #pragma unroll
    for (int r = 0; r < 2; r++) {
        #pragma unroll
        for (int nt = 0; nt < 4; nt++) {
            int x = x0 + nw*32 + nt*8 + 2*t4;
            float2 o0 = make_float2(tf32r(fmaxf(fmaf(c[r][nt][0], s0, bo0), 0.f)),
                                    tf32r(fmaxf(fmaf(c[r][nt][1], s0, bo0), 0.f)));
            float2 o1 = make_float2(tf32r(fmaxf(fmaf(c[r][nt][2], s1, bo1), 0.f)),
                                    tf32r(fmaxf(fmaf(c[r][nt][3], s1, bo1), 0.f)));
            *reinterpret_cast<float2*>(g_x1 + ((size_t)(n*32 + co0) * H + y0 + r) * W + x) = o0;
            *reinterpret_cast<float2*>(g_x1 + ((size_t)(n*32 + co1) * H + y0 + r) * W + x) = o1;
        }
    }
}

// ================= conv2: 32 -> 64, 3x3, pad 1, BN+ReLU — TF32 MMA =================
// block 256 = 4 M-warps x 2 N-warps. Tile: 64 couts x 64 px x 2 rows. Single-phase smem.
__global__ void __launch_bounds__(256) k_conv2(const float* __restrict__ w_unused) {
    __shared__ float sB[32][4][74];   // 37.9 KB; ci stride 296 ≡ 8 (mod 32) — conflict-free
    int t = threadIdx.x;
    int warp = t >> 5, lane = t & 31;
    int mw = warp & 3;
    int nw = warp >> 2;
    int g = lane >> 2, t4 = lane & 3;

    int x0 = blockIdx.x * 64;
    int y0 = blockIdx.y * 2;
    int n  = blockIdx.z;

    float c[2][4][4];
    #pragma unroll
    for (int r = 0; r < 2; r++)
        #pragma unroll
        for (int nt = 0; nt < 4; nt++) { c[r][nt][0]=0.f; c[r][nt][1]=0.f; c[r][nt][2]=0.f; c[r][nt][3]=0.f; }

    // single fill: 32 ci x 4 rows x 66 cols
    for (int i = t; i < 32*4*66; i += 256) {
        int ci = i / 264; int rem = i - ci*264;
        int r = rem / 66, xx = rem - r*66;
        int gy = y0 + r - 1, gx = x0 + xx - 1;
        float v = 0.f;
        if ((unsigned)gy < H && (unsigned)gx < W)
            v = g_x1[((size_t)(n*32 + ci) * H + gy) * W + gx];
        sB[ci][r][xx] = v;
    }
    __syncthreads();

    #pragma unroll
    for (int cc = 0; cc < 4; cc++) {
        #pragma unroll
        for (int ky = 0; ky < 3; ky++) {
            #pragma unroll
            for (int kx = 0; kx < 3; kx++) {
                int p = ky*3 + kx;
                int off = (((mw*9 + p)*4 + cc)*16)*8 + g*8 + t4;
                unsigned int a0 = g_wt2[off];
                unsigned int a1 = g_wt2[off + 64];
                unsigned int a2 = g_wt2[off + 4];
                unsigned int a3 = g_wt2[off + 68];
                #pragma unroll
                for (int r = 0; r < 2; r++) {
                    const float* bb = &sB[cc*8 + t4][ky + r][nw*32 + g + kx];
                    #pragma unroll
                    for (int nt = 0; nt < 4; nt++) {
                        unsigned int b0 = __float_as_uint(bb[nt*8]);
                        unsigned int b1 = __float_as_uint(bb[nt*8 + 4*4*74]);  // ci +4
                        asm volatile(
                            "mma.sync.aligned.m16n8k8.row.col.f32.tf32.tf32.f32 "
                            "{%0,%1,%2,%3}, {%4,%5,%6,%7}, {%8,%9}, {%0,%1,%2,%3};\n"
                            : "+f"(c[r][nt][0]), "+f"(c[r][nt][1]), "+f"(c[r][nt][2]), "+f"(c[r][nt][3])
                            : "r"(a0), "r"(a1), "r"(a2), "r"(a3), "r"(b0), "r"(b1));
                    }
                }
            }
        }
    }

    int co0 = mw*16 + g;
    int co1 = co0 + 8;
    float s0 = g_s2[co0], bo0 = g_bb2[co0];
    float s1 = g_s2[co1], bo1 = g_bb2[co1];
    #pragma unroll
    for (int r = 0; r < 2; r++) {
        #pragma unroll
        for (int nt = 0; nt < 4; nt++) {
            int x = x0 + nw*32 + nt*8 + 2*t4;
            float2 o0 = make_float2(fmaxf(fmaf(c[r][nt][0], s0, bo0), 0.f),
                                    fmaxf(fmaf(c[r][nt][1], s0, bo0), 0.f));
            float2 o1 = make_float2(fmaxf(fmaf(c[r][nt][2], s1, bo1), 0.f),
                                    fmaxf(fmaf(c[r][nt][3], s1, bo1), 0.f));
            *reinterpret_cast<float2*>(g_x2 + ((size_t)(n*64 + co0) * H + y0 + r) * W + x) = o0;
            *reinterpret_cast<float2*>(g_x2 + ((size_t)(n*64 + co1) * H + y0 + r) * W + x) = o1;
        }
    }
}

// ======== fused tail: conv3 (1x1, 64->8, ReLU) + softmax propagation + blend ========
// block 256 thr, output tile 64x16; aff computed for 66x18 halo tile in smem.
// grid (W/64, H/16, NB)
__global__ void __launch_bounds__(256) k_tail(const float* __restrict__ w3,
                                              const float* __restrict__ disp,
                                              float* __restrict__ out) {
    __shared__ float sAff[8][18][66];   // 38.0 KB
    __shared__ float sD[18][66];        //  4.8 KB
    __shared__ float sW[512];           //  2.0 KB
    int t = threadIdx.x;
    int x0 = blockIdx.x * 64;
    int y0 = blockIdx.y * 16;
    int n  = blockIdx.z;

    for (int i = t; i < 512; i += 256) sW[i] = w3[i];
    __syncthreads();

    // phase 1: conv3 at all 66x18 halo positions
    const float* xb = g_x2 + (size_t)(n*64) * HW;
    for (int pos = t; pos < 18*66; pos += 256) {
        int yy = pos / 66, xx = pos - yy*66;
        int gy = y0 + yy - 1, gx = x0 + xx - 1;
        float a[8];
        #pragma unroll
        for (int k = 0; k < 8; k++) a[k] = 0.f;
        float dv = 0.f;
        if ((unsigned)gy < H && (unsigned)gx < W) {
            size_t o = (size_t)gy * W + gx;
            #pragma unroll 8
            for (int ci = 0; ci < 64; ci++) {
                float v = xb[(size_t)ci * HW + o];
                #pragma unroll
                for (int k = 0; k < 8; k++)
                    a[k] = fmaf(sW[k*64 + ci], v, a[k]);
            }
            #pragma unroll
            for (int k = 0; k < 8; k++) a[k] = fmaxf(a[k], 0.f);
            dv = disp[(size_t)n * HW + o];
        }
        #pragma unroll
        for (int k = 0; k < 8; k++) sAff[k][yy][xx] = a[k];
        sD[yy][xx] = dv;
    }
    __syncthreads();

    // phase 2: softmax propagation + blend for the 64x16 interior
    const int dy[8] = { 1, 1, 1, 0, 0, -1, -1, -1 };
    const int dx[8] = { 1, 0,-1, 1,-1,  1,  0, -1 };
    for (int o = t; o < 64*16; o += 256) {
        int oy = o >> 6, ox = o & 63;
        int yy = oy + 1, xx = ox + 1;
        float g[8], dd[8];
        #pragma unroll
        for (int k = 0; k < 8; k++) {
            g[k]  = sAff[k][yy + dy[k]][xx + dx[k]];
            dd[k] = sD[yy + dy[k]][xx + dx[k]];
        }
        float m = g[0];
        #pragma unroll
        for (int k = 1; k < 8; k++) m = fmaxf(m, g[k]);
        float se = 0.f, sp = 0.f;
        #pragma unroll
        for (int k = 0; k < 8; k++) {
            float e = expf(g[k] - m);
            se += e;
            sp = fmaf(e, dd[k], sp);
        }
        float prop = sp / se;
        out[(size_t)n * HW + (size_t)(y0 + oy) * W + x0 + ox] = 0.3f * prop + 0.7f * sD[yy][xx];
    }
}

// ---------------- launch ----------------
extern "C" void kernel_launch(void* const* d_in, const int* in_sizes, int n_in,
                              void* d_out, int out_size) {
    const float* normal = (const float*)d_in[0];
    const float* left   = (const float*)d_in[1];
    const float* right  = (const float*)d_in[2];
    const float* disp   = (const float*)d_in[3];
    const float* w1 = (const float*)d_in[4];
    const float* g1 = (const float*)d_in[5];
    const float* b1 = (const float*)d_in[6];
    const float* m1 = (const float*)d_in[7];
    const float* v1 = (const float*)d_in[8];
    const float* w2 = (const float*)d_in[9];
    const float* g2 = (const float*)d_in[10];
    const float* b2 = (const float*)d_in[11];
    const float* m2 = (const float*)d_in[12];
    const float* v2 = (const float*)d_in[13];
    const float* w3 = (const float*)d_in[14];
    float* out = (float*)d_out;

    k_bnfold<<<1, 64>>>(g1, b1, m1, v1, g2, b2, m2, v2);
    k_wprep1<<<(32*12*9 + 255) / 256, 256>>>(w1);
    k_wprep2<<<(64*32*9 + 255) / 256, 256>>>(w2);

    k_pre<<<(NB*3*HW + 255) / 256, 256>>>(left, right, normal, disp);

    k_conv1<<<dim3(W/128, H/2, NB), 256>>>(w1);
    k_conv2<<<dim3(W/64, H/2, NB), 256>>>(w2);

    k_tail<<<dim3(W/64, H/16, NB), 256>>>(w3, disp, out);
}

// round 7
// speedup vs baseline: 3.1848x; 1.0214x over previous
#include <cuda_runtime.h>
#include <math.h>

#define NB 8
#define H 256
#define W 256
#define H2 512
#define W2 512
#define HW (H*W)

// ---------------- scratch (device globals; no allocation) ----------------
__device__ float g_featsP[NB*16*HW];   // features, padded to 16 ch (12..15 stay zero)
__device__ float g_x1[NB*32*HW];       // conv1 out (tf32-rounded)
__device__ float g_x2[NB*64*HW];       // conv2 out
__device__ float g_s1[32], g_bb1[32], g_s2[64], g_bb2[64]; // folded BN
__device__ unsigned int g_wt1[2*9*2*16*8];  // conv1 weights, tf32, frag-ordered
__device__ unsigned int g_wt2[4*9*4*16*8];  // conv2 weights, tf32, frag-ordered

__device__ __forceinline__ unsigned int f2tf32(float v) {
    unsigned int r; asm("cvt.rna.tf32.f32 %0, %1;" : "=r"(r) : "f"(v)); return r;
}
__device__ __forceinline__ float tf32r(float v) { return __uint_as_float(f2tf32(v)); }

// ---------------- setup: BN fold + both weight preps in ONE launch ----------------
__global__ void k_setup(const float* __restrict__ w1, const float* __restrict__ w2,
                        const float* __restrict__ g1, const float* __restrict__ b1,
                        const float* __restrict__ m1, const float* __restrict__ v1,
                        const float* __restrict__ g2, const float* __restrict__ b2,
                        const float* __restrict__ m2, const float* __restrict__ v2) {
    int idx = blockIdx.x * blockDim.x + threadIdx.x;
    if (idx < 32) { float s = g1[idx] * rsqrtf(v1[idx] + 1e-5f); g_s1[idx] = s; g_bb1[idx] = b1[idx] - m1[idx] * s; }
    else if (idx < 96) { int i = idx - 32; float s = g2[i] * rsqrtf(v2[i] + 1e-5f); g_s2[i] = s; g_bb2[i] = b2[i] - m2[i] * s; }
    int i1 = idx - 96;                       // wprep1: 32*12*9 = 3456
    if (i1 >= 0 && i1 < 3456) {
        int p  = i1 % 9;
        int ci = (i1 / 9) % 12;
        int co = i1 / 108;
        int m = co >> 4, r = co & 15;
        int cc = ci >> 3, k = ci & 7;
        g_wt1[(((m*9 + p)*2 + cc)*16 + r)*8 + k] = f2tf32(w1[(size_t)co*108 + ci*9 + p]);
    }
    int i2 = idx - 96 - 3456;                // wprep2: 64*32*9 = 18432
    if (i2 >= 0 && i2 < 18432) {
        int p  = i2 % 9;
        int ci = (i2 / 9) % 32;
        int co = i2 / 288;
        int m = co >> 4, r = co & 15;
        int cc = ci >> 3, k = ci & 7;
        g_wt2[(((m*9 + p)*4 + cc)*16 + r)*8 + k] = f2tf32(w2[(size_t)co*288 + ci*9 + p]);
    }
}

// ---------------- fused preprocessing ----------------
__device__ __forceinline__ float pool2(const float* row, int x2) {
    float2 a = *reinterpret_cast<const float2*>(row + x2);
    float2 b = *reinterpret_cast<const float2*>(row + x2 + W2);
    return 0.25f * (a.x + a.y + b.x + b.y);
}

__global__ void k_pre(const float* __restrict__ left, const float* __restrict__ right,
                      const float* __restrict__ normal, const float* __restrict__ disp) {
    int idx = blockIdx.x * blockDim.x + threadIdx.x;
    if (idx >= NB*3*HW) return;
    int x = idx & 255;
    int y = (idx >> 8) & 255;
    int nc = idx >> 16;
    int c = nc % 3, n = nc / 3;

    const float* rrow = right + ((size_t)(n*3 + c) * H2 + 2*y) * W2;
    const float* lrow = left  + ((size_t)(n*3 + c) * H2 + 2*y) * W2;
    float rv = pool2(rrow, 2*x);
    float l  = pool2(lrow, 2*x);

    size_t base = ((size_t)(n*16) * H + y) * W + x;
    g_featsP[base + (size_t)c * HW]     = tf32r(normal[((size_t)(n*3 + c) * H + y) * W + x]);
    g_featsP[base + (size_t)(3+c) * HW] = tf32r(l);
    g_featsP[base + (size_t)(6+c) * HW] = tf32r(rv);

    float d = disp[((size_t)n * H + y) * W + x];
    float xs = (float)x - d;
    float x0f = floorf(xs);
    float frac = xs - x0f;
    int x0i = (int)x0f;
    int x1i = x0i + 1;
    float v0 = (x0i >= 0 && x0i < W) ? 1.f : 0.f;
    float v1 = (x1i >= 0 && x1i < W) ? 1.f : 0.f;
    int x0c = min(max(x0i, 0), W-1);
    int x1c = min(max(x1i, 0), W-1);
    float r0 = pool2(rrow, 2*x0c);
    float r1 = pool2(rrow, 2*x1c);
    float warped = (r0 * v0) * (1.f - frac) + (r1 * v1) * frac;
    g_featsP[base + (size_t)(9+c) * HW] = tf32r(fabsf(l - warped));
}

// ================= conv1: 16(pad) -> 32, 3x3, pad 1, BN+ReLU — TF32 MMA =================
// Tile: 32 couts x 128 px x 2 rows. smem [row][ci][x], x from x0-4, 136 cols, float4 fill.
__global__ void __launch_bounds__(256) k_conv1(const float* __restrict__ w_unused) {
    __shared__ float sB[4][16][136];   // 34.8 KB; ci stride 136 ≡ 8 (mod 32): banks g+8*t4
    int t = threadIdx.x;
    int warp = t >> 5, lane = t & 31;
    int mw = warp & 1;
    int nw = warp >> 1;
    int g = lane >> 2, t4 = lane & 3;

    int x0 = blockIdx.x * 128;
    int y0 = blockIdx.y * 2;
    int n  = blockIdx.z;

    float c[2][4][4];
    #pragma unroll
    for (int r = 0; r < 2; r++)
        #pragma unroll
        for (int nt = 0; nt < 4; nt++) { c[r][nt][0]=0.f; c[r][nt][1]=0.f; c[r][nt][2]=0.f; c[r][nt][3]=0.f; }

    // vector fill: 4 rows x 16 ci x 34 float4 (groups fully in/out of range by construction)
    for (int i = t; i < 4*16*34; i += 256) {
        int row = i / 544; int rem = i - row*544;
        int ci = rem / 34, j = rem - ci*34;
        int gy = y0 + row - 1, gx0 = x0 - 4 + j*4;
        float4 v = make_float4(0.f, 0.f, 0.f, 0.f);
        if ((unsigned)gy < H && gx0 >= 0 && gx0 + 3 < W)
            v = *reinterpret_cast<const float4*>(&g_featsP[((size_t)(n*16 + ci) * H + gy) * W + gx0]);
        *reinterpret_cast<float4*>(&sB[row][ci][j*4]) = v;
    }
    __syncthreads();

    #pragma unroll
    for (int cc = 0; cc < 2; cc++) {
        #pragma unroll
        for (int ky = 0; ky < 3; ky++) {
            #pragma unroll
            for (int kx = 0; kx < 3; kx++) {
                int p = ky*3 + kx;
                int off = (((mw*9 + p)*2 + cc)*16)*8 + g*8 + t4;
                unsigned int a0 = g_wt1[off];
                unsigned int a1 = g_wt1[off + 64];
                unsigned int a2 = g_wt1[off + 4];
                unsigned int a3 = g_wt1[off + 68];
                #pragma unroll
                for (int r = 0; r < 2; r++) {
                    const float* bb = &sB[ky + r][cc*8 + t4][nw*32 + g + kx + 3];
                    #pragma unroll
                    for (int nt = 0; nt < 4; nt++) {
                        unsigned int b0 = __float_as_uint(bb[nt*8]);
                        unsigned int b1 = __float_as_uint(bb[nt*8 + 4*136]);  // ci +4
                        asm volatile(
                            "mma.sync.aligned.m16n8k8.row.col.f32.tf32.tf32.f32 "
                            "{%0,%1,%2,%3}, {%4,%5,%6,%7}, {%8,%9}, {%0,%1,%2,%3};\n"
                            : "+f"(c[r][nt][0]), "+f"(c[r][nt][1]), "+f"(c[r][nt][2]), "+f"(c[r][nt][3])
                            : "r"(a0), "r"(a1), "r"(a2), "r"(a3), "r"(b0), "r"(b1));
                    }
                }
            }
        }
    }

    int co0 = mw*16 + g;
    int co1 = co0 + 8;
    float s0 = g_s1[co0], bo0 = g_bb1[co0];
    float s1 = g_s1[co1], bo1 = g_bb1[co1];
    #pragma unroll
    for (int r = 0; r < 2; r++) {
        #pragma unroll
        for (int nt = 0; nt < 4; nt++) {
            int x = x0 + nw*32 + nt*8 + 2*t4;
            float2 o0 = make_float2(tf32r(fmaxf(fmaf(c[r][nt][0], s0, bo0), 0.f)),
                                    tf32r(fmaxf(fmaf(c[r][nt][1], s0, bo0), 0.f)));
            float2 o1 = make_float2(tf32r(fmaxf(fmaf(c[r][nt][2], s1, bo1), 0.f)),
                                    tf32r(fmaxf(fmaf(c[r][nt][3], s1, bo1), 0.f)));
            *reinterpret_cast<float2*>(g_x1 + ((size_t)(n*32 + co0) * H + y0 + r) * W + x) = o0;
            *reinterpret_cast<float2*>(g_x1 + ((size_t)(n*32 + co1) * H + y0 + r) * W + x) = o1;
        }
    }
}

// ================= conv2: 32 -> 64, 3x3, pad 1, BN+ReLU — TF32 MMA =================
// Tile: 64 couts x 64 px x 2 rows. smem [row][ci][x], x from x0-4, 72 cols, float4 fill.
__global__ void __launch_bounds__(256) k_conv2(const float* __restrict__ w_unused) {
    __shared__ float sB[4][32][72];   // 36.9 KB; ci stride 72 ≡ 8 (mod 32): banks g+8*t4
    int t = threadIdx.x;
    int warp = t >> 5, lane = t & 31;
    int mw = warp & 3;
    int nw = warp >> 2;
    int g = lane >> 2, t4 = lane & 3;

    int x0 = blockIdx.x * 64;
    int y0 = blockIdx.y * 2;
    int n  = blockIdx.z;

    float c[2][4][4];
    #pragma unroll
    for (int r = 0; r < 2; r++)
        #pragma unroll
        for (int nt = 0; nt < 4; nt++) { c[r][nt][0]=0.f; c[r][nt][1]=0.f; c[r][nt][2]=0.f; c[r][nt][3]=0.f; }

    // vector fill: 4 rows x 32 ci x 18 float4
    for (int i = t; i < 4*32*18; i += 256) {
        int row = i / 576; int rem = i - row*576;
        int ci = rem / 18, j = rem - ci*18;
        int gy = y0 + row - 1, gx0 = x0 - 4 + j*4;
        float4 v = make_float4(0.f, 0.f, 0.f, 0.f);
        if ((unsigned)gy < H && gx0 >= 0 && gx0 + 3 < W)
            v = *reinterpret_cast<const float4*>(&g_x1[((size_t)(n*32 + ci) * H + gy) * W + gx0]);
        *reinterpret_cast<float4*>(&sB[row][ci][j*4]) = v;
    }
    __syncthreads();

    #pragma unroll
    for (int cc = 0; cc < 4; cc++) {
        #pragma unroll
        for (int ky = 0; ky < 3; ky++) {
            #pragma unroll
            for (int kx = 0; kx < 3; kx++) {
                int p = ky*3 + kx;
                int off = (((mw*9 + p)*4 + cc)*16)*8 + g*8 + t4;
                unsigned int a0 = g_wt2[off];
                unsigned int a1 = g_wt2[off + 64];
                unsigned int a2 = g_wt2[off + 4];
                unsigned int a3 = g_wt2[off + 68];
                #pragma unroll
                for (int r = 0; r < 2; r++) {
                    const float* bb = &sB[ky + r][cc*8 + t4][nw*32 + g + kx + 3];
                    #pragma unroll
                    for (int nt = 0; nt < 4; nt++) {
                        unsigned int b0 = __float_as_uint(bb[nt*8]);
                        unsigned int b1 = __float_as_uint(bb[nt*8 + 4*72]);  // ci +4
                        asm volatile(
                            "mma.sync.aligned.m16n8k8.row.col.f32.tf32.tf32.f32 "
                            "{%0,%1,%2,%3}, {%4,%5,%6,%7}, {%8,%9}, {%0,%1,%2,%3};\n"
                            : "+f"(c[r][nt][0]), "+f"(c[r][nt][1]), "+f"(c[r][nt][2]), "+f"(c[r][nt][3])
                            : "r"(a0), "r"(a1), "r"(a2), "r"(a3), "r"(b0), "r"(b1));
                    }
                }
            }
        }
    }

    int co0 = mw*16 + g;
    int co1 = co0 + 8;
    float s0 = g_s2[co0], bo0 = g_bb2[co0];
    float s1 = g_s2[co1], bo1 = g_bb2[co1];
    #pragma unroll
    for (int r = 0; r < 2; r++) {
        #pragma unroll
        for (int nt = 0; nt < 4; nt++) {
            int x = x0 + nw*32 + nt*8 + 2*t4;
            float2 o0 = make_float2(fmaxf(fmaf(c[r][nt][0], s0, bo0), 0.f),
                                    fmaxf(fmaf(c[r][nt][1], s0, bo0), 0.f));
            float2 o1 = make_float2(fmaxf(fmaf(c[r][nt][2], s1, bo1), 0.f),
                                    fmaxf(fmaf(c[r][nt][3], s1, bo1), 0.f));
            *reinterpret_cast<float2*>(g_x2 + ((size_t)(n*64 + co0) * H + y0 + r) * W + x) = o0;
            *reinterpret_cast<float2*>(g_x2 + ((size_t)(n*64 + co1) * H + y0 + r) * W + x) = o1;
        }
    }
}

// ======== fused tail: conv3 (1x1, 64->8, ReLU) + softmax propagation + blend ========
// Output tile 64x16; aff computed vectorized (float4) on a 72x18 halo tile (x from x0-4).
__global__ void __launch_bounds__(256) k_tail(const float* __restrict__ w3,
                                              const float* __restrict__ disp,
                                              float* __restrict__ out) {
    __shared__ float sAff[8][18][72];   // 40.5 KB
    __shared__ float sD[18][72];        //  5.1 KB
    __shared__ float sW[512];           //  2.0 KB    (total 47.6 KB)
    int t = threadIdx.x;
    int x0 = blockIdx.x * 64;
    int y0 = blockIdx.y * 16;
    int n  = blockIdx.z;

    for (int i = t; i < 512; i += 256) sW[i] = w3[i];
    __syncthreads();

    // phase 1: conv3 for 18 rows x 18 float4-groups (all groups fully in/out of x-range)
    const float* xb = g_x2 + (size_t)(n*64) * HW;
    for (int task = t; task < 18*18; task += 256) {
        int yy = task / 18, jg = task - yy*18;
        int gy = y0 + yy - 1, gx0 = x0 - 4 + jg*4;
        float a[8][4];
        #pragma unroll
        for (int k = 0; k < 8; k++) { a[k][0]=0.f; a[k][1]=0.f; a[k][2]=0.f; a[k][3]=0.f; }
        float4 dv = make_float4(0.f, 0.f, 0.f, 0.f);
        if ((unsigned)gy < H && gx0 >= 0 && gx0 + 3 < W) {
            size_t o = (size_t)gy * W + gx0;
            #pragma unroll 8
            for (int ci = 0; ci < 64; ci++) {
                float4 v = *reinterpret_cast<const float4*>(&xb[(size_t)ci * HW + o]);
                #pragma unroll
                for (int k = 0; k < 8; k++) {
                    float wv = sW[k*64 + ci];
                    a[k][0] = fmaf(wv, v.x, a[k][0]);
                    a[k][1] = fmaf(wv, v.y, a[k][1]);
                    a[k][2] = fmaf(wv, v.z, a[k][2]);
                    a[k][3] = fmaf(wv, v.w, a[k][3]);
                }
            }
            #pragma unroll
            for (int k = 0; k < 8; k++) {
                a[k][0] = fmaxf(a[k][0], 0.f); a[k][1] = fmaxf(a[k][1], 0.f);
                a[k][2] = fmaxf(a[k][2], 0.f); a[k][3] = fmaxf(a[k][3], 0.f);
            }
            dv = *reinterpret_cast<const float4*>(&disp[(size_t)n * HW + o]);
        }
        #pragma unroll
        for (int k = 0; k < 8; k++)
            *reinterpret_cast<float4*>(&sAff[k][yy][jg*4]) = make_float4(a[k][0], a[k][1], a[k][2], a[k][3]);
        *reinterpret_cast<float4*>(&sD[yy][jg*4]) = dv;
    }
    __syncthreads();

    // phase 2: softmax propagation + blend for the 64x16 interior (xx offset +4 in smem)
    const int dy[8] = { 1, 1, 1, 0, 0, -1, -1, -1 };
    const int dx[8] = { 1, 0,-1, 1,-1,  1,  0, -1 };
    for (int o = t; o < 64*16; o += 256) {
        int oy = o >> 6, ox = o & 63;
        int yy = oy + 1, xx = ox + 4;
        float g[8], dd[8];
        #pragma unroll
        for (int k = 0; k < 8; k++) {
            g[k]  = sAff[k][yy + dy[k]][xx + dx[k]];
            dd[k] = sD[yy + dy[k]][xx + dx[k]];
        }
        float m = g[0];
        #pragma unroll
        for (int k = 1; k < 8; k++) m = fmaxf(m, g[k]);
        float se = 0.f, sp = 0.f;
        #pragma unroll
        for (int k = 0; k < 8; k++) {
            float e = expf(g[k] - m);
            se += e;
            sp = fmaf(e, dd[k], sp);
        }
        float prop = sp / se;
        out[(size_t)n * HW + (size_t)(y0 + oy) * W + x0 + ox] = 0.3f * prop + 0.7f * sD[yy][xx];
    }
}

// ---------------- launch ----------------
extern "C" void kernel_launch(void* const* d_in, const int* in_sizes, int n_in,
                              void* d_out, int out_size) {
    const float* normal = (const float*)d_in[0];
    const float* left   = (const float*)d_in[1];
    const float* right  = (const float*)d_in[2];
    const float* disp   = (const float*)d_in[3];
    const float* w1 = (const float*)d_in[4];
    const float* g1 = (const float*)d_in[5];
    const float* b1 = (const float*)d_in[6];
    const float* m1 = (const float*)d_in[7];
    const float* v1 = (const float*)d_in[8];
    const float* w2 = (const float*)d_in[9];
    const float* g2 = (const float*)d_in[10];
    const float* b2 = (const float*)d_in[11];
    const float* m2 = (const float*)d_in[12];
    const float* v2 = (const float*)d_in[13];
    const float* w3 = (const float*)d_in[14];
    float* out = (float*)d_out;

    k_setup<<<(96 + 3456 + 18432 + 255) / 256, 256>>>(w1, w2, g1, b1, m1, v1, g2, b2, m2, v2);

    k_pre<<<(NB*3*HW + 255) / 256, 256>>>(left, right, normal, disp);

    k_conv1<<<dim3(W/128, H/2, NB), 256>>>(w1);
    k_conv2<<<dim3(W/64, H/2, NB), 256>>>(w2);

    k_tail<<<dim3(W/64, H/16, NB), 256>>>(w3, disp, out);
}